// round 14
// baseline (speedup 1.0000x reference)
#include <cuda_runtime.h>
#include <cuda_fp16.h>
#include <cstdint>
#include <cstddef>

// Problem constants
#define SSZ  4096
#define BBZ  8
#define HHZ  1024
#define N3Z  3072
#define MMZ  32768          // S*B
#define KKZ  1024
#define CHN  (BBZ * HHZ)    // 8192 channels
#define CS   64             // scan chunk length
#define NC   (SSZ / CS)     // 64 chunks

// ---------------- device-global scratch (no allocations allowed) ----------
// Gate arrays: logically [S][CHN] since (s*8+b)*1024+hh == s*CHN + ch
__device__ float  g_gU[(size_t)MMZ * HHZ];      // 134 MB (u, fp32)
__device__ __half g_gF[(size_t)MMZ * HHZ];      // 64 MB (sigmoid(f), fp16)
__device__ __half g_gO[(size_t)MMZ * HHZ];      // 64 MB (sigmoid(o), fp16)
__device__ __half g_Ah[(size_t)MMZ * KKZ];      // 64 MB (x fp16, then h1 fp16)
__device__ __half g_W1h[(size_t)N3Z * KKZ];     // 6 MB
__device__ __half g_W2h[(size_t)N3Z * KKZ];     // 6 MB
__device__ float  g_scanP[(size_t)NC * CHN];
__device__ float  g_scanE[(size_t)NC * CHN];
__device__ float  g_scanC[(size_t)NC * CHN];

// ---------------- PTX helpers ---------------------------------------------
__device__ __forceinline__ uint32_t smem_u32(const void* p) {
    uint32_t a;
    asm("{ .reg .u64 t; cvta.to.shared.u64 t, %1; cvt.u32.u64 %0, t; }"
        : "=r"(a) : "l"(p));
    return a;
}

#define CP16(saddr, gptr) \
    asm volatile("cp.async.cg.shared.global [%0], [%1], 16;" \
                 :: "r"(saddr), "l"(gptr))
#define CP_COMMIT() asm volatile("cp.async.commit_group;" ::: "memory")
#define CP_WAIT(n)  asm volatile("cp.async.wait_group %0;" :: "n"(n) : "memory")

#define LDSM4(r0, r1, r2, r3, addr) \
    asm volatile("ldmatrix.sync.aligned.m8n8.x4.shared.b16 {%0,%1,%2,%3}, [%4];" \
                 : "=r"(r0), "=r"(r1), "=r"(r2), "=r"(r3) : "r"(addr))

#define MMAF16(d, a, b0, b1) \
    asm volatile("mma.sync.aligned.m16n8k16.row.col.f32.f16.f16.f32 " \
                 "{%0,%1,%2,%3},{%4,%5,%6,%7},{%8,%9},{%0,%1,%2,%3};" \
                 : "+f"((d)[0]), "+f"((d)[1]), "+f"((d)[2]), "+f"((d)[3]) \
                 : "r"((a)[0]), "r"((a)[1]), "r"((a)[2]), "r"((a)[3]), \
                   "r"(b0), "r"(b1))

__device__ __forceinline__ float sigm(float v) {
    return 1.0f / (1.0f + __expf(-v));
}
// inf-safe fast tanh: copysign(1 - 2/(exp(2|x|)+1), x)
__device__ __forceinline__ float tanh_fast(float x) {
    float e = __expf(2.0f * fabsf(x));      // overflows to +inf safely
    float t = 1.0f - 2.0f / (e + 1.0f);
    return copysignf(t, x);
}

// ---------------- GEMM: persistent CTAs, 128x128 tile, 2 CTAs/SM ----------
#define BM 128
#define BN 128
#define BK 64
#define NT (KKZ / BK)                 // 16 chunks per tile
#define NTILE_N (N3Z / BN)            // 24
#define NTILE_M (MMZ / BM)            // 256
#define NTILES (NTILE_N * NTILE_M)    // 6144
#define GRID_P 296                    // 2 CTAs x 148 SMs
#define OFF_A  0                      // A: 128 x 128B = 16 KB
#define OFF_B  16384                  // W: 128 x 128B = 16 KB
#define STAGE_BYTES 32768             // 32 KB
#define NSTG 3
#define SMEM_NEED (NSTG * STAGE_BYTES + 1024)   // ~97 KB + align pad

__device__ __forceinline__ uint32_t swz_rs(uint32_t row, uint32_t seg) {
    return row * 128u + (((seg ^ row) & 7u) << 4);
}

__global__ void __launch_bounds__(256, 2)
gemm_mma2(const __half* __restrict__ Ah, const __half* __restrict__ Wh,
          const float* __restrict__ bias,
          float* __restrict__ gU, __half* __restrict__ gF, __half* __restrict__ gO)
{
    extern __shared__ char smraw[];
    const uint32_t sb0 = smem_u32(smraw);
    const uint32_t sb  = (sb0 + 1023u) & ~1023u;

    const int tid  = threadIdx.x;
    const int wid  = tid >> 5;
    const int lane = tid & 31;
    const int wm   = wid >> 1;            // 0..3 (m), warp tile 32x64
    const int wn   = wid & 1;             // 0..1 (n)

    const int tile0  = blockIdx.x;
    const int ntiles = (NTILES - tile0 + GRID_P - 1) / GRID_P;
    const int nch    = ntiles * NT;       // linear k-chunk stream

    // load k-chunk c (tile tile0 + (c>>4)*GRID_P, chunk c&15) into buffer c%3
    auto load_stage = [&](int c) {
        const int tl = tile0 + (c >> 4) * GRID_P;
        const int t  = c & (NT - 1);
        const int bm = (tl / NTILE_N) * BM;
        const int bn = (tl % NTILE_N) * BN;
        const int k0 = t * BK;
        const uint32_t s0 = sb + (c % NSTG) * STAGE_BYTES;
        #pragma unroll
        for (int r = 0; r < 4; ++r) {
            const int idx = tid + r * 256;
            const uint32_t row = idx >> 3, seg = idx & 7;
            CP16(s0 + OFF_A + swz_rs(row, seg),
                 Ah + (size_t)(bm + row) * KKZ + k0 + seg * 8);
        }
        #pragma unroll
        for (int r = 0; r < 4; ++r) {
            const int idx = tid + r * 256;
            const uint32_t row = idx >> 3, seg = idx & 7;
            CP16(s0 + OFF_B + swz_rs(row, seg),
                 Wh + (size_t)(bn + row) * KKZ + k0 + seg * 8);
        }
    };

    const uint32_t a_row = (uint32_t)(wm * 32) + (lane & 15);
    const uint32_t a_kh  = (uint32_t)(lane >> 4);
    const uint32_t b_row = (uint32_t)(wn * 64) + (lane & 7) + ((lane >> 4) << 3);
    const uint32_t b_kh  = (uint32_t)((lane >> 3) & 1);

    float acc[2][8][4];
    #pragma unroll
    for (int mi = 0; mi < 2; ++mi)
        #pragma unroll
        for (int ni = 0; ni < 8; ++ni)
            #pragma unroll
            for (int j = 0; j < 4; ++j) acc[mi][ni][j] = 0.0f;

    load_stage(0); CP_COMMIT();
    load_stage(1); CP_COMMIT();

    #pragma unroll 1
    for (int c = 0; c < nch; ++c) {
        CP_WAIT(1);
        __syncthreads();
        if (c + 2 < nch) load_stage(c + 2);
        CP_COMMIT();                      // unconditional: group count stays exact

        const uint32_t s0 = sb + (c % NSTG) * STAGE_BYTES;

        #pragma unroll
        for (int ks = 0; ks < 4; ++ks) {
            const uint32_t a_seg = (uint32_t)(ks * 2) + a_kh;
            const uint32_t b_seg = (uint32_t)(ks * 2) + b_kh;
            uint32_t af[2][4], bf[4][4];
            #pragma unroll
            for (int mi = 0; mi < 2; ++mi) {
                const uint32_t so = swz_rs(a_row + mi * 16, a_seg);
                LDSM4(af[mi][0], af[mi][1], af[mi][2], af[mi][3], s0 + OFF_A + so);
            }
            #pragma unroll
            for (int nb = 0; nb < 4; ++nb) {
                const uint32_t so = swz_rs(b_row + nb * 16, b_seg);
                LDSM4(bf[nb][0], bf[nb][1], bf[nb][2], bf[nb][3], s0 + OFF_B + so);
            }
            #pragma unroll
            for (int mi = 0; mi < 2; ++mi)
                #pragma unroll
                for (int ni = 0; ni < 8; ++ni)
                    MMAF16(acc[mi][ni], af[mi],
                           bf[ni >> 1][2 * (ni & 1)], bf[ni >> 1][2 * (ni & 1) + 1]);
        }

        // ---- per-tile epilogue (overlaps next tile's in-flight loads) ----
        if ((c & (NT - 1)) == NT - 1) {
            const int tl  = tile0 + (c >> 4) * GRID_P;
            const int nb  = tl % NTILE_N;
            const int bm  = (tl / NTILE_N) * BM;
            const int creg = nb >> 3;             // 0=u, 1=f, 2=o
            const int cb   = (nb & 7) * 128;      // column block within gate
            const int bnn  = nb * BN;             // column in [0, 3072)
            #pragma unroll
            for (int mi = 0; mi < 2; ++mi) {
                const int r0 = bm + wm * 32 + mi * 16 + (lane >> 2);
                #pragma unroll
                for (int ni = 0; ni < 8; ++ni) {
                    const int cl = wn * 64 + ni * 8 + (lane & 3) * 2;
                    const float b0 = __ldg(bias + bnn + cl);
                    const float b1 = __ldg(bias + bnn + cl + 1);
                    float a0 = acc[mi][ni][0] + b0, a1 = acc[mi][ni][1] + b1;
                    float a2 = acc[mi][ni][2] + b0, a3 = acc[mi][ni][3] + b1;
                    const size_t o0 = (size_t)r0 * HHZ + cb + cl;
                    const size_t o1 = (size_t)(r0 + 8) * HHZ + cb + cl;
                    if (creg == 0) {
                        *(float2*)(gU + o0) = make_float2(a0, a1);
                        *(float2*)(gU + o1) = make_float2(a2, a3);
                    } else {
                        __half* dst = (creg == 1) ? gF : gO;
                        *(__half2*)(dst + o0) = __floats2half2_rn(sigm(a0), sigm(a1));
                        *(__half2*)(dst + o1) = __floats2half2_rn(sigm(a2), sigm(a3));
                    }
                    #pragma unroll
                    for (int j = 0; j < 4; ++j) acc[mi][ni][j] = 0.0f;
                }
            }
        }
    }
}

// ---------------- fp32 -> fp16 convert -------------------------------------
__global__ void tofp16_kernel(const float* __restrict__ in,
                              __half* __restrict__ out)
{
    size_t i = (size_t)blockIdx.x * blockDim.x + threadIdx.x;
    float4 v = ((const float4*)in)[i];
    ((__half2*)out)[2 * i + 0] = __floats2half2_rn(v.x, v.y);
    ((__half2*)out)[2 * i + 1] = __floats2half2_rn(v.z, v.w);
}

// ---------------- W[K,N] -> Wt[N,K] transpose + fp16 convert ---------------
__global__ void wtrans_kernel(const float* __restrict__ W,
                              __half* __restrict__ hi)
{
    __shared__ float t[32][33];
    const int n0 = blockIdx.x * 32, k0 = blockIdx.y * 32;
    const int tx = threadIdx.x, ty = threadIdx.y;   // 32 x 8
    #pragma unroll
    for (int i = 0; i < 4; ++i)
        t[ty + i*8][tx] = W[(size_t)(k0 + ty + i*8) * N3Z + n0 + tx];
    __syncthreads();
    #pragma unroll
    for (int i = 0; i < 4; ++i) {
        float v = t[tx][ty + i*8];
        hi[(size_t)(n0 + ty + i*8) * KKZ + k0 + tx] = __float2half_rn(v);
    }
}

// ---------------- chunked SRU scan (4 channels / thread) --------------------
__device__ __forceinline__ float4 ldh4(const __half* p) {
    uint2 raw = *(const uint2*)p;
    __half2 h0 = *(__half2*)&raw.x;
    __half2 h1 = *(__half2*)&raw.y;
    float2 f0 = __half22float2(h0);
    float2 f1 = __half22float2(h1);
    return make_float4(f0.x, f0.y, f1.x, f1.y);
}
__device__ __forceinline__ void sth4(__half* p, float4 v) {
    uint2 raw;
    *(__half2*)&raw.x = __floats2half2_rn(v.x, v.y);
    *(__half2*)&raw.y = __floats2half2_rn(v.z, v.w);
    *(uint2*)p = raw;
}

// Pass 1: per (4-channel group, chunk) partial scan from 0; prod(f), endpoint.
__global__ void scan_pass1(const float* __restrict__ gU, const __half* __restrict__ gF,
                           float* __restrict__ P, float* __restrict__ E)
{
    const int idx = blockIdx.x * blockDim.x + threadIdx.x;   // 0..NC*CHN/4-1
    const int chv = idx & (CHN / 4 - 1);
    const int j   = idx >> 11;
    const int ch  = chv << 2;

    float4 c = make_float4(0.f, 0.f, 0.f, 0.f);
    float4 p = make_float4(1.f, 1.f, 1.f, 1.f);
    const int s0 = j * CS;
    #pragma unroll 4
    for (int s = s0; s < s0 + CS; ++s) {
        const size_t off = (size_t)s * CHN + ch;
        float4 u = *(const float4*)(gU + off);
        float4 f = ldh4(gF + off);
        c.x = f.x * c.x + (1.f - f.x) * u.x;  p.x *= f.x;
        c.y = f.y * c.y + (1.f - f.y) * u.y;  p.y *= f.y;
        c.z = f.z * c.z + (1.f - f.z) * u.z;  p.z *= f.z;
        c.w = f.w * c.w + (1.f - f.w) * u.w;  p.w *= f.w;
    }
    *(float4*)(P + (size_t)j * CHN + ch) = p;
    *(float4*)(E + (size_t)j * CHN + ch) = c;
}

// Pass 2: sequential carry propagation across chunks (exact).
__global__ void scan_pass2(const float* __restrict__ P, const float* __restrict__ E,
                           const float* __restrict__ c0,
                           float* __restrict__ carry, float* __restrict__ clast)
{
    const int ch = (blockIdx.x * blockDim.x + threadIdx.x) << 2;  // 4-ch groups
    float4 c = *(const float4*)(c0 + ch);
    #pragma unroll 8
    for (int j = 0; j < NC; ++j) {
        const size_t off = (size_t)j * CHN + ch;
        *(float4*)(carry + off) = c;
        float4 e = *(const float4*)(E + off);
        float4 p = *(const float4*)(P + off);
        c.x = e.x + p.x * c.x;  c.y = e.y + p.y * c.y;
        c.z = e.z + p.z * c.z;  c.w = e.w + p.w * c.w;
    }
    *(float4*)(clast + ch) = c;
}

// Pass 3, layer 1: x fp32, h out fp16 (becomes next layer's A).
__global__ void scan_pass3_a(const float* __restrict__ gU, const __half* __restrict__ gF,
                             const __half* __restrict__ gO,
                             const float* __restrict__ xin,
                             const float* __restrict__ carry,
                             __half* __restrict__ hout_h)
{
    const int idx = blockIdx.x * blockDim.x + threadIdx.x;
    const int chv = idx & (CHN / 4 - 1);
    const int j   = idx >> 11;
    const int ch  = chv << 2;

    float4 c = *(const float4*)(carry + (size_t)j * CHN + ch);
    const int s0 = j * CS;
    #pragma unroll 4
    for (int s = s0; s < s0 + CS; ++s) {
        const size_t off = (size_t)s * CHN + ch;
        float4 u = *(const float4*)(gU + off);
        float4 f = ldh4(gF + off);
        float4 o = ldh4(gO + off);
        float4 x = *(const float4*)(xin + off);
        c.x = f.x * c.x + (1.f - f.x) * u.x;
        c.y = f.y * c.y + (1.f - f.y) * u.y;
        c.z = f.z * c.z + (1.f - f.z) * u.z;
        c.w = f.w * c.w + (1.f - f.w) * u.w;
        float4 h;
        h.x = o.x * tanh_fast(c.x) + (1.f - o.x) * x.x;
        h.y = o.y * tanh_fast(c.y) + (1.f - o.y) * x.y;
        h.z = o.z * tanh_fast(c.z) + (1.f - o.z) * x.z;
        h.w = o.w * tanh_fast(c.w) + (1.f - o.w) * x.w;
        sth4(hout_h + off, h);
    }
}

// Pass 3, layer 2: x fp16 (h1), h out fp32 (final output).
__global__ void scan_pass3_b(const float* __restrict__ gU, const __half* __restrict__ gF,
                             const __half* __restrict__ gO,
                             const __half* __restrict__ xin,
                             const float* __restrict__ carry,
                             float* __restrict__ hout)
{
    const int idx = blockIdx.x * blockDim.x + threadIdx.x;
    const int chv = idx & (CHN / 4 - 1);
    const int j   = idx >> 11;
    const int ch  = chv << 2;

    float4 c = *(const float4*)(carry + (size_t)j * CHN + ch);
    const int s0 = j * CS;
    #pragma unroll 4
    for (int s = s0; s < s0 + CS; ++s) {
        const size_t off = (size_t)s * CHN + ch;
        float4 u = *(const float4*)(gU + off);
        float4 f = ldh4(gF + off);
        float4 o = ldh4(gO + off);
        float4 x = ldh4(xin + off);
        c.x = f.x * c.x + (1.f - f.x) * u.x;
        c.y = f.y * c.y + (1.f - f.y) * u.y;
        c.z = f.z * c.z + (1.f - f.z) * u.z;
        c.w = f.w * c.w + (1.f - f.w) * u.w;
        float4 h;
        h.x = o.x * tanh_fast(c.x) + (1.f - o.x) * x.x;
        h.y = o.y * tanh_fast(c.y) + (1.f - o.y) * x.y;
        h.z = o.z * tanh_fast(c.z) + (1.f - o.z) * x.z;
        h.w = o.w * tanh_fast(c.w) + (1.f - o.w) * x.w;
        *(float4*)(hout + off) = h;
    }
}

// ---------------- launch ---------------------------------------------------
extern "C" void kernel_launch(void* const* d_in, const int* in_sizes, int n_in,
                              void* d_out, int out_size)
{
    const float* x  = (const float*)d_in[0];
    const float* h0 = (const float*)d_in[1];
    const float* W1 = (const float*)d_in[2];
    const float* b1 = (const float*)d_in[3];
    const float* W2 = (const float*)d_in[4];
    const float* b2 = (const float*)d_in[5];

    float* out    = (float*)d_out;
    float* h2     = out;
    float* hidden = out + (size_t)SSZ * CHN;

    float *gU, *sP, *sE, *sC;
    __half *gF, *gO, *Ah, *W1h, *W2h;
    cudaGetSymbolAddress((void**)&gU,  g_gU);
    cudaGetSymbolAddress((void**)&gF,  g_gF);
    cudaGetSymbolAddress((void**)&gO,  g_gO);
    cudaGetSymbolAddress((void**)&Ah,  g_Ah);
    cudaGetSymbolAddress((void**)&W1h, g_W1h);
    cudaGetSymbolAddress((void**)&W2h, g_W2h);
    cudaGetSymbolAddress((void**)&sP,  g_scanP);
    cudaGetSymbolAddress((void**)&sE,  g_scanE);
    cudaGetSymbolAddress((void**)&sC,  g_scanC);

    cudaFuncSetAttribute(gemm_mma2, cudaFuncAttributeMaxDynamicSharedMemorySize,
                         SMEM_NEED);

    const int ncv = (MMZ * KKZ / 4) / 256;
    dim3 wgrid(N3Z / 32, KKZ / 32), wblk(32, 8);
    const int pgrid = (NC * CHN / 4) / 256;      // 512 blocks
    const int cgrid = (CHN / 4) / 256;           // 8 blocks

    // weight prep
    wtrans_kernel<<<wgrid, wblk>>>(W1, W1h);
    wtrans_kernel<<<wgrid, wblk>>>(W2, W2h);

    // Layer 1
    tofp16_kernel<<<ncv, 256>>>(x, Ah);
    gemm_mma2<<<GRID_P, 256, SMEM_NEED>>>(Ah, W1h, b1, gU, gF, gO);
    scan_pass1<<<pgrid, 256>>>(gU, gF, sP, sE);
    scan_pass2<<<cgrid, 256>>>(sP, sE, h0, sC, hidden);
    scan_pass3_a<<<pgrid, 256>>>(gU, gF, gO, x, sC, Ah);   // h1 -> fp16 over A

    // Layer 2
    gemm_mma2<<<GRID_P, 256, SMEM_NEED>>>(Ah, W2h, b2, gU, gF, gO);
    scan_pass1<<<pgrid, 256>>>(gU, gF, sP, sE);
    scan_pass2<<<cgrid, 256>>>(sP, sE, h0 + CHN, sC, hidden + CHN);
    scan_pass3_b<<<pgrid, 256>>>(gU, gF, gO, Ah, sC, h2);
}

// round 15
// speedup vs baseline: 1.6343x; 1.6343x over previous
#include <cuda_runtime.h>
#include <cuda_fp16.h>
#include <cstdint>
#include <cstddef>

// Problem constants
#define SSZ  4096
#define BBZ  8
#define HHZ  1024
#define N3Z  3072
#define MMZ  32768          // S*B
#define KKZ  1024
#define CHN  (BBZ * HHZ)    // 8192 channels
#define CS   64             // scan chunk length
#define NC   (SSZ / CS)     // 64 chunks

// ---------------- device-global scratch (no allocations allowed) ----------
// Gate arrays: logically [S][CHN] since (s*8+b)*1024+hh == s*CHN + ch
__device__ __half g_gU[(size_t)MMZ * HHZ];      // 64 MB (u, fp16)
__device__ __half g_gF[(size_t)MMZ * HHZ];      // 64 MB (sigmoid(f), fp16)
__device__ __half g_gO[(size_t)MMZ * HHZ];      // 64 MB (sigmoid(o), fp16)
__device__ __half g_Ah[(size_t)MMZ * KKZ];      // 64 MB (x fp16, then h1 fp16)
__device__ __half g_W1h[(size_t)N3Z * KKZ];     // 6 MB
__device__ __half g_W2h[(size_t)N3Z * KKZ];     // 6 MB
__device__ float  g_scanP[(size_t)NC * CHN];
__device__ float  g_scanE[(size_t)NC * CHN];
__device__ float  g_scanC[(size_t)NC * CHN];

// ---------------- PTX helpers ---------------------------------------------
__device__ __forceinline__ uint32_t smem_u32(const void* p) {
    uint32_t a;
    asm("{ .reg .u64 t; cvta.to.shared.u64 t, %1; cvt.u32.u64 %0, t; }"
        : "=r"(a) : "l"(p));
    return a;
}

#define CP16(saddr, gptr) \
    asm volatile("cp.async.cg.shared.global [%0], [%1], 16;" \
                 :: "r"(saddr), "l"(gptr))
#define CP_COMMIT() asm volatile("cp.async.commit_group;" ::: "memory")
#define CP_WAIT(n)  asm volatile("cp.async.wait_group %0;" :: "n"(n) : "memory")

#define LDSM4(r0, r1, r2, r3, addr) \
    asm volatile("ldmatrix.sync.aligned.m8n8.x4.shared.b16 {%0,%1,%2,%3}, [%4];" \
                 : "=r"(r0), "=r"(r1), "=r"(r2), "=r"(r3) : "r"(addr))

#define MMAF16(d, a, b0, b1) \
    asm volatile("mma.sync.aligned.m16n8k16.row.col.f32.f16.f16.f32 " \
                 "{%0,%1,%2,%3},{%4,%5,%6,%7},{%8,%9},{%0,%1,%2,%3};" \
                 : "+f"((d)[0]), "+f"((d)[1]), "+f"((d)[2]), "+f"((d)[3]) \
                 : "r"((a)[0]), "r"((a)[1]), "r"((a)[2]), "r"((a)[3]), \
                   "r"(b0), "r"(b1))

__device__ __forceinline__ float sigm(float v) {
    return 1.0f / (1.0f + __expf(-v));
}
// inf-safe fast tanh: copysign(1 - 2/(exp(2|x|)+1), x)
__device__ __forceinline__ float tanh_fast(float x) {
    float e = __expf(2.0f * fabsf(x));      // overflows to +inf safely
    float t = 1.0f - 2.0f / (e + 1.0f);
    return copysignf(t, x);
}

// ---------------- GEMM: 128x128 CTA, 2 CTAs/SM, 3-stage cp.async ----------
// (R13 structure — known good: grid (24, 256), per-tile epilogue)
#define BM 128
#define BN 128
#define BK 64
#define NT (KKZ / BK)                 // 16
#define OFF_A  0                      // A: 128 x 128B = 16 KB
#define OFF_B  16384                  // W: 128 x 128B = 16 KB
#define STAGE_BYTES 32768             // 32 KB
#define NSTG 3
#define STAGES_OFF 1024
#define SMEM_NEED (STAGES_OFF + NSTG * STAGE_BYTES + 1024)   // ~100 KB

__device__ __forceinline__ uint32_t swz_rs(uint32_t row, uint32_t seg) {
    return row * 128u + (((seg ^ row) & 7u) << 4);
}

__global__ void __launch_bounds__(256, 2)
gemm_mma2(const __half* __restrict__ Ah, const __half* __restrict__ Wh,
          const float* __restrict__ bias,
          __half* __restrict__ gU, __half* __restrict__ gF, __half* __restrict__ gO)
{
    extern __shared__ char smraw[];
    const uint32_t sb0 = smem_u32(smraw);
    const uint32_t sb  = (sb0 + 1023u) & ~1023u;
    char* smp = smraw + (sb - sb0);

    const int tid  = threadIdx.x;
    const int wid  = tid >> 5;
    const int lane = tid & 31;
    const int wm   = wid >> 1;            // 0..3 (m), warp tile 32x64
    const int wn   = wid & 1;             // 0..1 (n)
    const int bn   = blockIdx.x * BN;
    const int bm   = blockIdx.y * BM;

    if (tid < 128) ((float*)smp)[tid] = bias[bn + tid];

    // loader: 8 cp16 per thread per stage (A:4, B:4)
    auto load_stage = [&](int t, int st) {
        const int k0 = t * BK;
        const uint32_t s0 = sb + STAGES_OFF + st * STAGE_BYTES;
        #pragma unroll
        for (int r = 0; r < 4; ++r) {
            const int idx = tid + r * 256;
            const uint32_t row = idx >> 3, seg = idx & 7;
            CP16(s0 + OFF_A + swz_rs(row, seg),
                 Ah + (size_t)(bm + row) * KKZ + k0 + seg * 8);
        }
        #pragma unroll
        for (int r = 0; r < 4; ++r) {
            const int idx = tid + r * 256;
            const uint32_t row = idx >> 3, seg = idx & 7;
            CP16(s0 + OFF_B + swz_rs(row, seg),
                 Wh + (size_t)(bn + row) * KKZ + k0 + seg * 8);
        }
    };

    const uint32_t a_row = (uint32_t)(wm * 32) + (lane & 15);
    const uint32_t a_kh  = (uint32_t)(lane >> 4);
    const uint32_t b_row = (uint32_t)(wn * 64) + (lane & 7) + ((lane >> 4) << 3);
    const uint32_t b_kh  = (uint32_t)((lane >> 3) & 1);

    float acc[2][8][4];
    #pragma unroll
    for (int mi = 0; mi < 2; ++mi)
        #pragma unroll
        for (int ni = 0; ni < 8; ++ni)
            #pragma unroll
            for (int j = 0; j < 4; ++j) acc[mi][ni][j] = 0.0f;

    load_stage(0, 0); CP_COMMIT();
    load_stage(1, 1); CP_COMMIT();

    #pragma unroll 1
    for (int t = 0; t < NT; ++t) {
        CP_WAIT(1);
        __syncthreads();
        if (t + 2 < NT) load_stage(t + 2, (t + 2) % NSTG);
        CP_COMMIT();                      // unconditional: group count stays exact

        const uint32_t s0 = sb + STAGES_OFF + (t % NSTG) * STAGE_BYTES;

        #pragma unroll
        for (int ks = 0; ks < 4; ++ks) {
            const uint32_t a_seg = (uint32_t)(ks * 2) + a_kh;
            const uint32_t b_seg = (uint32_t)(ks * 2) + b_kh;
            uint32_t af[2][4], bf[4][4];
            #pragma unroll
            for (int mi = 0; mi < 2; ++mi) {
                const uint32_t so = swz_rs(a_row + mi * 16, a_seg);
                LDSM4(af[mi][0], af[mi][1], af[mi][2], af[mi][3], s0 + OFF_A + so);
            }
            #pragma unroll
            for (int nb = 0; nb < 4; ++nb) {
                const uint32_t so = swz_rs(b_row + nb * 16, b_seg);
                LDSM4(bf[nb][0], bf[nb][1], bf[nb][2], bf[nb][3], s0 + OFF_B + so);
            }
            #pragma unroll
            for (int mi = 0; mi < 2; ++mi)
                #pragma unroll
                for (int ni = 0; ni < 8; ++ni)
                    MMAF16(acc[mi][ni], af[mi],
                           bf[ni >> 1][2 * (ni & 1)], bf[ni >> 1][2 * (ni & 1) + 1]);
        }
    }

    // ---- gate-typed epilogue (all gates stored fp16; u raw, f/o sigmoid) --
    // blockIdx.x in [0,24): >>3 selects gate (0=u,1=f,2=o), &7 -> 128-col block.
    const int creg = blockIdx.x >> 3;
    const int cb   = (blockIdx.x & 7) * 128;
    __half* dst = (creg == 0) ? gU : ((creg == 1) ? gF : gO);
    const float* bsm = (const float*)smp;
    #pragma unroll
    for (int mi = 0; mi < 2; ++mi) {
        const int r0 = bm + wm * 32 + mi * 16 + (lane >> 2);
        #pragma unroll
        for (int ni = 0; ni < 8; ++ni) {
            const int cl = wn * 64 + ni * 8 + (lane & 3) * 2;
            const float b0 = bsm[cl], b1 = bsm[cl + 1];
            float a0 = acc[mi][ni][0] + b0, a1 = acc[mi][ni][1] + b1;
            float a2 = acc[mi][ni][2] + b0, a3 = acc[mi][ni][3] + b1;
            if (creg != 0) {
                a0 = sigm(a0); a1 = sigm(a1); a2 = sigm(a2); a3 = sigm(a3);
            }
            const size_t o0 = (size_t)r0 * HHZ + cb + cl;
            const size_t o1 = (size_t)(r0 + 8) * HHZ + cb + cl;
            *(__half2*)(dst + o0) = __floats2half2_rn(a0, a1);
            *(__half2*)(dst + o1) = __floats2half2_rn(a2, a3);
        }
    }
}

// ---------------- fp32 -> fp16 convert -------------------------------------
__global__ void tofp16_kernel(const float* __restrict__ in,
                              __half* __restrict__ out)
{
    size_t i = (size_t)blockIdx.x * blockDim.x + threadIdx.x;
    float4 v = ((const float4*)in)[i];
    ((__half2*)out)[2 * i + 0] = __floats2half2_rn(v.x, v.y);
    ((__half2*)out)[2 * i + 1] = __floats2half2_rn(v.z, v.w);
}

// ---------------- W[K,N] -> Wt[N,K] transpose + fp16 convert ---------------
__global__ void wtrans_kernel(const float* __restrict__ W,
                              __half* __restrict__ hi)
{
    __shared__ float t[32][33];
    const int n0 = blockIdx.x * 32, k0 = blockIdx.y * 32;
    const int tx = threadIdx.x, ty = threadIdx.y;   // 32 x 8
    #pragma unroll
    for (int i = 0; i < 4; ++i)
        t[ty + i*8][tx] = W[(size_t)(k0 + ty + i*8) * N3Z + n0 + tx];
    __syncthreads();
    #pragma unroll
    for (int i = 0; i < 4; ++i) {
        float v = t[tx][ty + i*8];
        hi[(size_t)(n0 + ty + i*8) * KKZ + k0 + tx] = __float2half_rn(v);
    }
}

// ---------------- chunked SRU scan (4 channels / thread) --------------------
__device__ __forceinline__ float4 ldh4(const __half* p) {
    uint2 raw = *(const uint2*)p;
    __half2 h0 = *(__half2*)&raw.x;
    __half2 h1 = *(__half2*)&raw.y;
    float2 f0 = __half22float2(h0);
    float2 f1 = __half22float2(h1);
    return make_float4(f0.x, f0.y, f1.x, f1.y);
}
__device__ __forceinline__ void sth4(__half* p, float4 v) {
    uint2 raw;
    *(__half2*)&raw.x = __floats2half2_rn(v.x, v.y);
    *(__half2*)&raw.y = __floats2half2_rn(v.z, v.w);
    *(uint2*)p = raw;
}

// Pass 1: per (4-channel group, chunk) partial scan from 0; prod(f), endpoint.
__global__ void scan_pass1(const __half* __restrict__ gU, const __half* __restrict__ gF,
                           float* __restrict__ P, float* __restrict__ E)
{
    const int idx = blockIdx.x * blockDim.x + threadIdx.x;   // 0..NC*CHN/4-1
    const int chv = idx & (CHN / 4 - 1);
    const int j   = idx >> 11;
    const int ch  = chv << 2;

    float4 c = make_float4(0.f, 0.f, 0.f, 0.f);
    float4 p = make_float4(1.f, 1.f, 1.f, 1.f);
    const int s0 = j * CS;
    #pragma unroll 4
    for (int s = s0; s < s0 + CS; ++s) {
        const size_t off = (size_t)s * CHN + ch;
        float4 u = ldh4(gU + off);
        float4 f = ldh4(gF + off);
        c.x = f.x * c.x + (1.f - f.x) * u.x;  p.x *= f.x;
        c.y = f.y * c.y + (1.f - f.y) * u.y;  p.y *= f.y;
        c.z = f.z * c.z + (1.f - f.z) * u.z;  p.z *= f.z;
        c.w = f.w * c.w + (1.f - f.w) * u.w;  p.w *= f.w;
    }
    *(float4*)(P + (size_t)j * CHN + ch) = p;
    *(float4*)(E + (size_t)j * CHN + ch) = c;
}

// Pass 2: sequential carry propagation across chunks (exact).
__global__ void scan_pass2(const float* __restrict__ P, const float* __restrict__ E,
                           const float* __restrict__ c0,
                           float* __restrict__ carry, float* __restrict__ clast)
{
    const int ch = (blockIdx.x * blockDim.x + threadIdx.x) << 2;  // 4-ch groups
    float4 c = *(const float4*)(c0 + ch);
    #pragma unroll 8
    for (int j = 0; j < NC; ++j) {
        const size_t off = (size_t)j * CHN + ch;
        *(float4*)(carry + off) = c;
        float4 e = *(const float4*)(E + off);
        float4 p = *(const float4*)(P + off);
        c.x = e.x + p.x * c.x;  c.y = e.y + p.y * c.y;
        c.z = e.z + p.z * c.z;  c.w = e.w + p.w * c.w;
    }
    *(float4*)(clast + ch) = c;
}

// Pass 3, layer 1: x fp16 (Ah copy of x), h out fp16 IN PLACE over Ah.
// Per-thread read-then-write of the same addresses; no cross-thread overlap.
__global__ void scan_pass3_a(const __half* __restrict__ gU, const __half* __restrict__ gF,
                             const __half* __restrict__ gO,
                             const float* __restrict__ carry,
                             __half* __restrict__ xh)     // in: x fp16, out: h1 fp16
{
    const int idx = blockIdx.x * blockDim.x + threadIdx.x;
    const int chv = idx & (CHN / 4 - 1);
    const int j   = idx >> 11;
    const int ch  = chv << 2;

    float4 c = *(const float4*)(carry + (size_t)j * CHN + ch);
    const int s0 = j * CS;
    #pragma unroll 4
    for (int s = s0; s < s0 + CS; ++s) {
        const size_t off = (size_t)s * CHN + ch;
        float4 u = ldh4(gU + off);
        float4 f = ldh4(gF + off);
        float4 o = ldh4(gO + off);
        float4 x = ldh4(xh + off);
        c.x = f.x * c.x + (1.f - f.x) * u.x;
        c.y = f.y * c.y + (1.f - f.y) * u.y;
        c.z = f.z * c.z + (1.f - f.z) * u.z;
        c.w = f.w * c.w + (1.f - f.w) * u.w;
        float4 h;
        h.x = o.x * tanh_fast(c.x) + (1.f - o.x) * x.x;
        h.y = o.y * tanh_fast(c.y) + (1.f - o.y) * x.y;
        h.z = o.z * tanh_fast(c.z) + (1.f - o.z) * x.z;
        h.w = o.w * tanh_fast(c.w) + (1.f - o.w) * x.w;
        sth4(xh + off, h);
    }
}

// Pass 3, layer 2: x fp16 (h1), h out fp32 (final output).
__global__ void scan_pass3_b(const __half* __restrict__ gU, const __half* __restrict__ gF,
                             const __half* __restrict__ gO,
                             const __half* __restrict__ xin,
                             const float* __restrict__ carry,
                             float* __restrict__ hout)
{
    const int idx = blockIdx.x * blockDim.x + threadIdx.x;
    const int chv = idx & (CHN / 4 - 1);
    const int j   = idx >> 11;
    const int ch  = chv << 2;

    float4 c = *(const float4*)(carry + (size_t)j * CHN + ch);
    const int s0 = j * CS;
    #pragma unroll 4
    for (int s = s0; s < s0 + CS; ++s) {
        const size_t off = (size_t)s * CHN + ch;
        float4 u = ldh4(gU + off);
        float4 f = ldh4(gF + off);
        float4 o = ldh4(gO + off);
        float4 x = ldh4(xin + off);
        c.x = f.x * c.x + (1.f - f.x) * u.x;
        c.y = f.y * c.y + (1.f - f.y) * u.y;
        c.z = f.z * c.z + (1.f - f.z) * u.z;
        c.w = f.w * c.w + (1.f - f.w) * u.w;
        float4 h;
        h.x = o.x * tanh_fast(c.x) + (1.f - o.x) * x.x;
        h.y = o.y * tanh_fast(c.y) + (1.f - o.y) * x.y;
        h.z = o.z * tanh_fast(c.z) + (1.f - o.z) * x.z;
        h.w = o.w * tanh_fast(c.w) + (1.f - o.w) * x.w;
        *(float4*)(hout + off) = h;
    }
}

// ---------------- launch ---------------------------------------------------
extern "C" void kernel_launch(void* const* d_in, const int* in_sizes, int n_in,
                              void* d_out, int out_size)
{
    const float* x  = (const float*)d_in[0];
    const float* h0 = (const float*)d_in[1];
    const float* W1 = (const float*)d_in[2];
    const float* b1 = (const float*)d_in[3];
    const float* W2 = (const float*)d_in[4];
    const float* b2 = (const float*)d_in[5];

    float* out    = (float*)d_out;
    float* h2     = out;
    float* hidden = out + (size_t)SSZ * CHN;

    float *sP, *sE, *sC;
    __half *gU, *gF, *gO, *Ah, *W1h, *W2h;
    cudaGetSymbolAddress((void**)&gU,  g_gU);
    cudaGetSymbolAddress((void**)&gF,  g_gF);
    cudaGetSymbolAddress((void**)&gO,  g_gO);
    cudaGetSymbolAddress((void**)&Ah,  g_Ah);
    cudaGetSymbolAddress((void**)&W1h, g_W1h);
    cudaGetSymbolAddress((void**)&W2h, g_W2h);
    cudaGetSymbolAddress((void**)&sP,  g_scanP);
    cudaGetSymbolAddress((void**)&sE,  g_scanE);
    cudaGetSymbolAddress((void**)&sC,  g_scanC);

    cudaFuncSetAttribute(gemm_mma2, cudaFuncAttributeMaxDynamicSharedMemorySize,
                         SMEM_NEED);

    const int ncv = (MMZ * KKZ / 4) / 256;
    dim3 wgrid(N3Z / 32, KKZ / 32), wblk(32, 8);
    dim3 ggrid(N3Z / BN, MMZ / BM);              // 24 x 256 = 6144 CTAs
    const int pgrid = (NC * CHN / 4) / 256;      // 512 blocks
    const int cgrid = (CHN / 4) / 256;           // 8 blocks

    // weight prep
    wtrans_kernel<<<wgrid, wblk>>>(W1, W1h);
    wtrans_kernel<<<wgrid, wblk>>>(W2, W2h);

    // Layer 1
    tofp16_kernel<<<ncv, 256>>>(x, Ah);
    gemm_mma2<<<ggrid, 256, SMEM_NEED>>>(Ah, W1h, b1, gU, gF, gO);
    scan_pass1<<<pgrid, 256>>>(gU, gF, sP, sE);
    scan_pass2<<<cgrid, 256>>>(sP, sE, h0, sC, hidden);
    scan_pass3_a<<<pgrid, 256>>>(gU, gF, gO, sC, Ah);   // h1 fp16 in place of x

    // Layer 2
    gemm_mma2<<<ggrid, 256, SMEM_NEED>>>(Ah, W2h, b2, gU, gF, gO);
    scan_pass1<<<pgrid, 256>>>(gU, gF, sP, sE);
    scan_pass2<<<cgrid, 256>>>(sP, sE, h0 + CHN, sC, hidden + CHN);
    scan_pass3_b<<<pgrid, 256>>>(gU, gF, gO, Ah, sC, h2);
}